// round 8
// baseline (speedup 1.0000x reference)
#include <cuda_runtime.h>
#include <math.h>

#define NN 50000
#define NE 800000
#define MB 148           // mega blocks: one per SM, all co-resident
#define MT 512           // mega threads per block; 148*512 = 75776 >= NN

// ---- device scratch ----
__device__ float4 g_h[NN * 16];     // h = x@W, [NN,64] as float4
__device__ float  g_s1[NN];         // dot(h[n], a[:64])
__device__ float  g_s2[NN];         // dot(h[n], a[64:])
__device__ int    g_cnt[NN];        // in-degree
__device__ int    g_off[NN];        // exclusive prefix (CSR row start)
__device__ int    g_cur[NN];        // running cursor for sort
__device__ int2   g_srt[NE];        // sorted records: (src node j, expv bits)
__device__ int    g_bsum[MB];       // per-block sums
__device__ int    g_bbase[MB];      // exclusive scan of block sums
__device__ float  g_sum;            // sum of exp(logits)
__device__ unsigned g_bar[4];       // grid-barrier arrival counters (reset by gemm)

// ---------------- K1: h = x@W + per-node scores; prologue zeroes CSR state ----------------
#define NPB 338   // 148*338 = 50024 >= NN
__global__ void __launch_bounds__(256, 1)
k_gemm(const float* __restrict__ x,
       const float* __restrict__ W,
       const float* __restrict__ attn) {
    __shared__ ulonglong2 Ws2[128 * 16];
    __shared__ float aws[128];
    const int t = threadIdx.x;
    const int gt = blockIdx.x * 256 + t;

    // prologue: reset per-replay state (runs before k_mega in stream order)
    for (int i = gt; i < NN; i += 148 * 256) g_cnt[i] = 0;
    if (gt == 0) {
        g_sum = 0.f;
        g_bar[0] = 0; g_bar[1] = 0; g_bar[2] = 0; g_bar[3] = 0;
    }

    {
        const float4* W4 = (const float4*)W;
        float4* Ws4 = (float4*)Ws2;
        for (int i = t; i < 2048; i += 256) Ws4[i] = W4[i];
        if (t < 128) aws[t] = attn[t];
    }
    __syncthreads();

    const int base = blockIdx.x * NPB;
    const int n0 = base + 2 * t;
    if (2 * t >= NPB || n0 >= NN) return;
    const int n1 = n0 + 1;
    const size_t r0 = (size_t)n0;
    const size_t r1 = (size_t)((n1 < NN) ? n1 : n0);

    unsigned long long accA[32], accB[32];
    #pragma unroll
    for (int c = 0; c < 32; c++) { accA[c] = 0ull; accB[c] = 0ull; }

    const float4* x4 = (const float4*)x;
    #pragma unroll 1
    for (int k4 = 0; k4 < 32; k4++) {
        float4 xa = x4[r0 * 32 + k4];
        float4 xb = x4[r1 * 32 + k4];
        #pragma unroll
        for (int s = 0; s < 4; s++) {
            float fa = (s == 0) ? xa.x : (s == 1) ? xa.y : (s == 2) ? xa.z : xa.w;
            float fb = (s == 0) ? xb.x : (s == 1) ? xb.y : (s == 2) ? xb.z : xb.w;
            unsigned long long pa, pb;
            asm("mov.b64 %0, {%1, %1};" : "=l"(pa) : "f"(fa));
            asm("mov.b64 %0, {%1, %1};" : "=l"(pb) : "f"(fb));
            const ulonglong2* wk = Ws2 + (k4 * 4 + s) * 16;
            #pragma unroll
            for (int c = 0; c < 16; c++) {
                ulonglong2 wv = wk[c];
                asm("fma.rn.f32x2 %0, %1, %2, %0;" : "+l"(accA[2*c])   : "l"(pa), "l"(wv.x));
                asm("fma.rn.f32x2 %0, %1, %2, %0;" : "+l"(accA[2*c+1]) : "l"(pa), "l"(wv.y));
                asm("fma.rn.f32x2 %0, %1, %2, %0;" : "+l"(accB[2*c])   : "l"(pb), "l"(wv.x));
                asm("fma.rn.f32x2 %0, %1, %2, %0;" : "+l"(accB[2*c+1]) : "l"(pb), "l"(wv.y));
            }
        }
    }

    {
        float s1 = 0.f, s2 = 0.f;
        #pragma unroll
        for (int q = 0; q < 16; q++) {
            float4 v;
            asm("mov.b64 {%0, %1}, %2;" : "=f"(v.x), "=f"(v.y) : "l"(accA[2*q]));
            asm("mov.b64 {%0, %1}, %2;" : "=f"(v.z), "=f"(v.w) : "l"(accA[2*q+1]));
            g_h[r0 * 16 + q] = v;
            s1 += v.x*aws[4*q] + v.y*aws[4*q+1] + v.z*aws[4*q+2] + v.w*aws[4*q+3];
            s2 += v.x*aws[64+4*q] + v.y*aws[64+4*q+1] + v.z*aws[64+4*q+2] + v.w*aws[64+4*q+3];
        }
        g_s1[n0] = s1; g_s2[n0] = s2;
    }
    if (n1 < NN) {
        float s1 = 0.f, s2 = 0.f;
        #pragma unroll
        for (int q = 0; q < 16; q++) {
            float4 v;
            asm("mov.b64 {%0, %1}, %2;" : "=f"(v.x), "=f"(v.y) : "l"(accB[2*q]));
            asm("mov.b64 {%0, %1}, %2;" : "=f"(v.z), "=f"(v.w) : "l"(accB[2*q+1]));
            g_h[(size_t)n1 * 16 + q] = v;
            s1 += v.x*aws[4*q] + v.y*aws[4*q+1] + v.z*aws[4*q+2] + v.w*aws[4*q+3];
            s2 += v.x*aws[64+4*q] + v.y*aws[64+4*q+1] + v.z*aws[64+4*q+2] + v.w*aws[64+4*q+3];
        }
        g_s1[n1] = s1; g_s2[n1] = s2;
    }
}

// ---------------- grid barrier (all MB blocks guaranteed co-resident) ----------------
__device__ __forceinline__ void gridsync(int p) {
    __syncthreads();
    if (threadIdx.x == 0) {
        __threadfence();
        atomicAdd(&g_bar[p], 1u);
        while (atomicAdd(&g_bar[p], 0u) < (unsigned)MB) { }
        __threadfence();
    }
    __syncthreads();
}

// ---------------- K2: fused count + scan + sort (persistent, 148 blocks) ----------------
__global__ void __launch_bounds__(MT)
k_mega(const int* __restrict__ eidx) {
    __shared__ int sm[MT];
    __shared__ float wr[MT / 32];
    const int b = blockIdx.x, t = threadIdx.x;
    const int gt = b * MT + t;
    const int nth = MB * MT;

    // phase A: destination histogram
    for (int e = gt; e < NE; e += nth)
        atomicAdd(&g_cnt[__ldg(eidx + e)], 1);
    gridsync(0);

    // phase B1: local exclusive scan of this block's MT nodes
    const int n = gt;                       // node id (blocks tile nodes contiguously)
    int v = (n < NN) ? __ldcg(&g_cnt[n]) : 0;
    sm[t] = v;
    __syncthreads();
    #pragma unroll
    for (int off = 1; off < MT; off <<= 1) {
        int add = (t >= off) ? sm[t - off] : 0;
        __syncthreads();
        sm[t] += add;
        __syncthreads();
    }
    if (t == MT - 1) g_bsum[b] = sm[MT - 1];
    const int local_ex = sm[t] - v;
    gridsync(1);

    // phase B2: block 0 scans the 148 block sums
    if (b == 0) {
        int vv = (t < MB) ? __ldcg(&g_bsum[t]) : 0;
        sm[t] = vv;
        __syncthreads();
        #pragma unroll
        for (int off = 1; off < MT; off <<= 1) {
            int add = (t >= off) ? sm[t - off] : 0;
            __syncthreads();
            sm[t] += add;
            __syncthreads();
        }
        if (t < MB) g_bbase[t] = sm[t] - vv;
    }
    gridsync(2);

    // phase B3: write CSR offsets + cursors
    if (n < NN) {
        int o = __ldcg(&g_bbase[b]) + local_ex;
        g_off[n] = o;
        g_cur[n] = o;
    }
    gridsync(3);

    // phase C: fused expv + counting-sort + global sum
    float lsum = 0.f;
    for (int e = gt; e < NE; e += nth) {
        int i = __ldg(eidx + e);
        int j = __ldg(eidx + NE + e);
        float l = g_s1[i] + g_s2[j];
        l = (l > 0.f) ? l : 0.2f * l;       // leaky_relu 0.2
        float ex = __expf(l);
        lsum += ex;
        int pos = atomicAdd(&g_cur[i], 1);
        g_srt[pos] = make_int2(j, __float_as_int(ex));
    }
    #pragma unroll
    for (int o = 16; o > 0; o >>= 1) lsum += __shfl_down_sync(0xffffffffu, lsum, o);
    int w = t >> 5, lane = t & 31;
    if (lane == 0) wr[w] = lsum;
    __syncthreads();
    if (w == 0) {
        float s = (lane < MT / 32) ? wr[lane] : 0.f;
        #pragma unroll
        for (int o = 8; o > 0; o >>= 1) s += __shfl_down_sync(0xffffffffu, s, o);
        if (lane == 0) atomicAdd(&g_sum, s);
    }
}

// ---------------- K3: per-node gather (1 warp/node, 2 records in flight) ----------------
__global__ void k_gather(float* __restrict__ out) {
    int gt = blockIdx.x * blockDim.x + threadIdx.x;
    int lane = threadIdx.x & 31;
    int n = gt >> 5;
    if (n >= NN) return;
    int l16 = lane & 15;
    int sub = lane >> 4;

    float inv = 1.0f / g_sum;
    int beg = g_off[n];
    int cnt = g_cnt[n];

    float4 acc = make_float4(0.f, 0.f, 0.f, 0.f);
    int k = sub;
    int2 rec = (k < cnt) ? __ldg(&g_srt[beg + k]) : make_int2(0, 0);
    while (k < cnt) {
        int2 cur = rec;
        int kn = k + 2;
        if (kn < cnt) rec = __ldg(&g_srt[beg + kn]);
        float ex = __int_as_float(cur.y);
        float4 hv = g_h[(size_t)cur.x * 16 + l16];
        acc.x += hv.x * ex; acc.y += hv.y * ex;
        acc.z += hv.z * ex; acc.w += hv.w * ex;
        k = kn;
    }
    acc.x += __shfl_xor_sync(0xffffffffu, acc.x, 16);
    acc.y += __shfl_xor_sync(0xffffffffu, acc.y, 16);
    acc.z += __shfl_xor_sync(0xffffffffu, acc.z, 16);
    acc.w += __shfl_xor_sync(0xffffffffu, acc.w, 16);
    acc.x *= inv; acc.y *= inv; acc.z *= inv; acc.w *= inv;

    float4* o = (float4*)out + (size_t)n * 128;
    #pragma unroll
    for (int q = 0; q < 4; q++) o[lane + 32 * q] = acc;
}

extern "C" void kernel_launch(void* const* d_in, const int* in_sizes, int n_in,
                              void* d_out, int out_size) {
    const float* x    = (const float*)d_in[0];
    const int*   eidx = (const int*)d_in[1];
    const float* W    = (const float*)d_in[2];
    const float* attn = (const float*)d_in[3];
    float* out = (float*)d_out;

    k_gemm<<<148, 256>>>(x, W, attn);
    k_mega<<<MB, MT>>>(eidx);
    k_gather<<<(NN * 32 + 255) / 256, 256>>>(out);
}